// round 8
// baseline (speedup 1.0000x reference)
#include <cuda_runtime.h>

typedef unsigned long long u64t;
typedef unsigned int u32t;

// Problem constants (fixed shapes from reference setup_inputs)
#define NB 2
#define NS 4
#define NTIME 256
#define NRECV 64
#define NPROB (NB*NS*NRECV)   // 512 independent sinkhorn problems
#define NPTS  256             // points per cloud
#define NPAIR 128             // column pairs
#define NSTEPS 24

#define LOG2E_F 1.4426950408889634f
#define LN2_F   0.6931471805599453f
#define DT_F    0.001f
#define EPSMIN_F 1e-4f        // BLUR^2
#define RATIO_F 0.25f         // SCALING^2

__device__ float g_div[NPROB];

__device__ __forceinline__ float ex2f(float x){ float y; asm("ex2.approx.ftz.f32 %0, %1;" : "=f"(y) : "f"(x)); return y; }
__device__ __forceinline__ float lg2f(float x){ float y; asm("lg2.approx.ftz.f32 %0, %1;" : "=f"(y) : "f"(x)); return y; }
__device__ __forceinline__ float rcpf(float x){ float y; asm("rcp.approx.ftz.f32 %0, %1;" : "=f"(y) : "f"(x)); return y; }

// packed f32x2 helpers (sm_100+ packed-FP32; only mul/add/fma exist — no packed max)
__device__ __forceinline__ u64t pack2(float lo, float hi){ u64t r; asm("mov.b64 %0, {%1,%2};" : "=l"(r) : "f"(lo), "f"(hi)); return r; }
__device__ __forceinline__ void unpack2(u64t v, float& lo, float& hi){ asm("mov.b64 {%0,%1}, %2;" : "=f"(lo), "=f"(hi) : "l"(v)); }
__device__ __forceinline__ u64t fma2(u64t a, u64t b, u64t c){ u64t r; asm("fma.rn.f32x2 %0, %1, %2, %3;" : "=l"(r) : "l"(a), "l"(b), "l"(c)); return r; }
__device__ __forceinline__ u64t add2(u64t a, u64t b){ u64t r; asm("add.rn.f32x2 %0, %1, %2;" : "=l"(r) : "l"(a), "l"(b)); return r; }

// 16B shared load straight into two packed 64-bit regs: (y0,y1) and (t0,t1)
#define LDS2(yv, tv, base, off) \
    asm("ld.shared.v2.b64 {%0,%1}, [%2+%3];" : "=l"(yv), "=l"(tv) : "r"(base), "n"(off))

struct SinkSmem {
    float4 H[NPAIR];                     // (y_j, y_{j+1}, t_j, t_{j+1}) per pair
    float  xo[NPTS];                     // obs amplitudes
    float  xs[NPTS];                     // syn amplitudes
    float  F[NPTS], G[NPTS], PX[NPTS], PY[NPTS];
    float  red[32];
};

__device__ __forceinline__ float warpSum(float v){
    #pragma unroll
    for (int o = 16; o; o >>= 1) v += __shfl_xor_sync(0xffffffffu, v, o);
    return v;
}
__device__ __forceinline__ float warpMax(float v){
    #pragma unroll
    for (int o = 16; o; o >>= 1) v = fmaxf(v, __shfl_xor_sync(0xffffffffu, v, o));
    return v;
}
__device__ __forceinline__ float warpMin(float v){
    #pragma unroll
    for (int o = 16; o; o >>= 1) v = fminf(v, __shfl_xor_sync(0xffffffffu, v, o));
    return v;
}

__device__ __forceinline__ float blockSum(float v, float* red){
    v = warpSum(v);
    int w = threadIdx.x >> 5, l = threadIdx.x & 31;
    if (l == 0) red[w] = v;
    __syncthreads();
    if (w == 0) {
        float t = (l < 8) ? red[l] : 0.f;
        t = warpSum(t);
        if (l == 0) red[0] = t;
    }
    __syncthreads();
    v = red[0];
    __syncthreads();
    return v;
}
__device__ __forceinline__ float blockMax(float v, float* red){
    v = warpMax(v);
    int w = threadIdx.x >> 5, l = threadIdx.x & 31;
    if (l == 0) red[w] = v;
    __syncthreads();
    if (w == 0) {
        float t = (l < 8) ? red[l] : -3.4e38f;
        t = warpMax(t);
        if (l == 0) red[0] = t;
    }
    __syncthreads();
    v = red[0];
    __syncthreads();
    return v;
}
__device__ __forceinline__ float blockMin(float v, float* red){
    v = warpMin(v);
    int w = threadIdx.x >> 5, l = threadIdx.x & 31;
    if (l == 0) red[w] = v;
    __syncthreads();
    if (w == 0) {
        float t = (l < 8) ? red[l] : 3.4e38f;
        t = warpMin(t);
        if (l == 0) red[0] = t;
    }
    __syncthreads();
    v = red[0];
    __syncthreads();
    return v;
}

// softmin over 256 columns, log2 domain, packed f32x2 inner loops.
// exponent(j) = la2 + pot_j*ie2 - ie2*(0.5(ti-tj)^2 + 0.5(xi-yj)^2)
//   col term t_j = la2 + pot_j*ie2 - 0.5*y_j^2*ie2 - c2*j^2   (in smem H)
//   per-pair    + xsc*y_j + u*j   (xsc = xi*ie2, u = 2*c2*i)
//   per-row consts fold back as +0.5*||X_i||^2 in the result.
__device__ __forceinline__ float softmin256p(
    const float* __restrict__ pot, const float* __restrict__ yc,
    SinkSmem& sm, u32t Hb,
    float xi, float ie2, float c2, float eps, float la2)
{
    const int tid = threadIdx.x;
    __syncthreads();   // previous users of H are done
    {
        float yv = yc[tid];
        float jv = (float)tid;
        float tv = la2 + pot[tid]*ie2 - (0.5f*yv*yv)*ie2 - c2*jv*jv;
        float* Hf = (float*)sm.H;
        int p = tid >> 1, h = tid & 1;
        Hf[4*p + h]     = yv;
        Hf[4*p + 2 + h] = tv;
    }
    __syncthreads();

    const float u   = 2.0f*c2*(float)tid;
    const float xsc = xi*ie2;
    const u64t u2   = pack2(u, u);
    const u64t xsc2 = pack2(xsc, xsc);

    u64t ko[8];
    #pragma unroll
    for (int k = 0; k < 8; k++) ko[k] = pack2((float)(2*k), (float)(2*k));

    // ---- pass 1: running max (4 scalar accumulators, free unpack of the pair) ----
    float m0 = -3.0e38f, m1 = -3.0e38f, m2 = -3.0e38f, m3 = -3.0e38f;
    #pragma unroll 1
    for (int p8 = 0; p8 < NPAIR; p8 += 8) {
        u32t ab = Hb + (u32t)p8 * 16u;
        float jb = (float)(2*p8);
        u64t jb2 = pack2(jb, jb + 1.0f);
        u64t y2, t2, b, a;
        float a0, a1;
        #define P1STEP(K, MA, MB) \
            LDS2(y2, t2, ab, (K)*16); \
            b = fma2(u2, add2(jb2, ko[K]), t2); \
            a = fma2(xsc2, y2, b); \
            unpack2(a, a0, a1); \
            MA = fmaxf(MA, a0); MB = fmaxf(MB, a1);
        P1STEP(0,m0,m1) P1STEP(1,m2,m3) P1STEP(2,m0,m1) P1STEP(3,m2,m3)
        P1STEP(4,m0,m1) P1STEP(5,m2,m3) P1STEP(6,m0,m1) P1STEP(7,m2,m3)
        #undef P1STEP
    }
    const float m = fmaxf(fmaxf(m0, m1), fmaxf(m2, m3));

    // ---- pass 2: sum of exp2(a - m) with -m folded into the j coordinate ----
    // j' = j - m/u  =>  u*j' = u*j - m. For u==0 (row 0): ueff=1e-20,
    // 1e-20*(j - m*1e38-safe) ~= -m exactly to fp32; no overflow (|m|<3e18).
    // The uniform per-row rcp error on m cancels through m + log2(s).
    const float ueff = fmaxf(u, 1e-20f);
    const u64t  ue2  = pack2(ueff, ueff);
    const float mru  = -m * rcpf(ueff);
    u64t sA = pack2(0.f, 0.f), sB = sA;
    #pragma unroll 1
    for (int p8 = 0; p8 < NPAIR; p8 += 8) {   // j' re-based every 8 pairs: no drift
        u32t ab = Hb + (u32t)p8 * 16u;
        float jb = (float)(2*p8) + mru;
        u64t jb2 = pack2(jb, jb + 1.0f);
        u64t y2, t2, b, a;
        float a0, a1, e0, e1;
        #define P2STEP(K, S) \
            LDS2(y2, t2, ab, (K)*16); \
            b = fma2(ue2, add2(jb2, ko[K]), t2); \
            a = fma2(xsc2, y2, b); \
            unpack2(a, a0, a1); \
            e0 = ex2f(a0); e1 = ex2f(a1); \
            S = add2(S, pack2(e0, e1));
        P2STEP(0,sA) P2STEP(1,sB) P2STEP(2,sA) P2STEP(3,sB)
        P2STEP(4,sA) P2STEP(5,sB) P2STEP(6,sA) P2STEP(7,sB)
        #undef P2STEP
    }
    float s;
    { float a0,a1,b0,b1; unpack2(sA,a0,a1); unpack2(sB,b0,b1);
      s = (a0 + a1) + (b0 + b1); }

    float ti = (float)tid * DT_F;
    return fmaf(-eps * LN2_F, m + lg2f(s), 0.5f*(ti*ti + xi*xi));
}

__global__ void __launch_bounds__(256, 4)
sink_main(const float* __restrict__ syn, const float* __restrict__ obs)
{
    __shared__ SinkSmem sm;
    const int p   = blockIdx.x;         // 0..511
    const int tid = threadIdx.x;        // row index 0..255
    const int bs  = p / NRECV;          // b*NS + s
    const int r   = p - bs * NRECV;

    u32t Hb;
    asm("{ .reg .u64 t; cvta.to.shared.u64 t, %1; cvt.u32.u64 %0, t; }"
        : "=r"(Hb) : "l"((void*)sm.H));

    const size_t base = (size_t)bs * NTIME * NRECV + r;
    const float xobs = obs[base + (size_t)tid * NRECV];
    const float xsyn = syn[base + (size_t)tid * NRECV];
    sm.xo[tid] = xobs;
    sm.xs[tid] = xsyn;
    sm.F[tid] = 0.f; sm.G[tid] = 0.f; sm.PX[tid] = 0.f; sm.PY[tid] = 0.f;
    __syncthreads();

    // trace mask + diameter
    float sabs_o = blockSum(fabsf(xobs), sm.red);
    float sabs_s = blockSum(fabsf(xsyn), sm.red);
    float vmax   = blockMax(fmaxf(xobs, xsyn), sm.red);
    float vmin   = blockMin(fminf(xobs, xsyn), sm.red);
    const bool masked = (sabs_o == 0.f) && (sabs_s == 0.f);

    const float trange   = (float)(NTIME - 1) * DT_F;
    const float diameter = fmaxf(trange, vmax - vmin);
    const float eps0     = diameter * diameter;           // P = 2
    const float la2      = -lg2f((float)NPTS);

    float fi = 0.f, gi = 0.f, pxi = 0.f, pyi = 0.f;
    float eps_raw = eps0;

    for (int k = 0; k < NSTEPS; k++) {
        const float eps = fmaxf(eps_raw, EPSMIN_F);
        eps_raw *= RATIO_F;
        const float ie2 = LOG2E_F / eps;
        const float c2  = 0.5f * DT_F * DT_F * ie2;

        // all four softmins read OLD potentials (scan-step semantics)
        fi  = softmin256p(sm.G,  sm.xs, sm, Hb, xobs, ie2, c2, eps, la2);
        gi  = softmin256p(sm.F,  sm.xo, sm, Hb, xsyn, ie2, c2, eps, la2);
        pxi = 0.5f * (pxi + softmin256p(sm.PX, sm.xo, sm, Hb, xobs, ie2, c2, eps, la2));
        pyi = 0.5f * (pyi + softmin256p(sm.PY, sm.xs, sm, Hb, xsyn, ie2, c2, eps, la2));

        __syncthreads();   // everyone done reading old potentials
        sm.F[tid] = fi; sm.G[tid] = gi; sm.PX[tid] = pxi; sm.PY[tid] = pyi;
    }
    __syncthreads();

    // S = sum w*(f - px) + sum w*(g - py), w = 1/n
    float contrib = (fi - pxi + gi - pyi) * (1.0f / (float)NPTS);
    float div = blockSum(contrib, sm.red);
    if (tid == 0) g_div[p] = masked ? 0.f : div;
}

// Deterministic final reduction: one block per batch, 256 problems each.
__global__ void __launch_bounds__(256)
sink_finalize(float* __restrict__ out)
{
    __shared__ float red[32];
    const int b = blockIdx.x;
    float v = g_div[b * (NS * NRECV) + threadIdx.x];
    v = blockSum(v, red);
    if (threadIdx.x == 0) out[b] = v;
}

extern "C" void kernel_launch(void* const* d_in, const int* in_sizes, int n_in,
                              void* d_out, int out_size)
{
    const float* syn = (const float*)d_in[0];   // syn_data [B,S,NT,NR]
    const float* obs = (const float*)d_in[1];   // obs_data [B,S,NT,NR]
    float* out = (float*)d_out;                 // [B] float32

    sink_main<<<NPROB, 256>>>(syn, obs);
    sink_finalize<<<NB, 256>>>(out);
}